// round 17
// baseline (speedup 1.0000x reference)
#include <cuda_runtime.h>
#include <cuda_bf16.h>
#include <cfloat>
#include <math.h>
#include <stdint.h>

#define T_LEN   65536
#define DIM_A   8
#define DIM_C   16
#define NTRANS  (T_LEN - 1)
#define CHUNK   256
#define G_CHUNKS 256
#define NSUPER  16

static const size_t OFF_ALPHA = 0;
static const size_t OFF_BETA  = (size_t)T_LEN * DIM_C;
static const size_t OFF_TRS   = 2ull * T_LEN * DIM_C;
static const size_t OFF_PIS   = OFF_TRS + (size_t)NTRANS * DIM_C * DIM_C;
static const size_t OFF_ENT   = OFF_PIS + (size_t)T_LEN * DIM_C;

// ---------------- device scratch ----------------
__device__ __nv_bfloat16 g_sH [(size_t)T_LEN * 64];
__device__ __nv_bfloat16 g_sL [(size_t)T_LEN * 64];
__device__ float g_Cmat[G_CHUNKS * 256];
__device__ float g_P  [G_CHUNKS * 256];
__device__ float g_Suf[G_CHUNKS * 256];
__device__ float g_Vs[(NSUPER + 1) * 16];
__device__ float g_Wsv[(NSUPER + 1) * 16];
__device__ float g_tr0[16];

#define WT_NPAD 384
#define WT_KPAD 256
#define WT_SZ   (WT_NPAD * WT_KPAD)
__device__ __nv_bfloat16 g_wtH[6 * WT_SZ];
__device__ __nv_bfloat16 g_wtL[6 * WT_SZ];

// ---------------- helpers ----------------
__device__ __forceinline__ uint32_t s2u(const void* p) {
    uint32_t a;
    asm("{ .reg .u64 t; cvta.to.shared.u64 t, %1; cvt.u32.u64 %0, t; }" : "=r"(a) : "l"(p));
    return a;
}
__device__ __forceinline__ uint32_t pack2(__nv_bfloat16 a, __nv_bfloat16 b) {
    return (uint32_t)__bfloat16_as_ushort(a) | ((uint32_t)__bfloat16_as_ushort(b) << 16);
}
__device__ __forceinline__ void cpa16(uint32_t d, const void* s) {
    asm volatile("cp.async.cg.shared.global [%0], [%1], 16;" :: "r"(d), "l"(s) : "memory");
}
#define CP_COMMIT() asm volatile("cp.async.commit_group;" ::: "memory")
#define LDM4(r, a) \
    asm volatile("ldmatrix.sync.aligned.m8n8.x4.shared.b16 {%0,%1,%2,%3}, [%4];" \
        : "=r"((r)[0]), "=r"((r)[1]), "=r"((r)[2]), "=r"((r)[3]) : "r"(a))
__device__ __forceinline__ void mma16816(float c[4], const uint32_t a[4], const uint32_t b[2]) {
    asm volatile(
        "mma.sync.aligned.m16n8k16.row.col.f32.bf16.bf16.f32 "
        "{%0,%1,%2,%3}, {%4,%5,%6,%7}, {%8,%9}, {%0,%1,%2,%3};\n"
        : "+f"(c[0]), "+f"(c[1]), "+f"(c[2]), "+f"(c[3])
        : "r"(a[0]), "r"(a[1]), "r"(a[2]), "r"(a[3]), "r"(b[0]), "r"(b[1]));
}
#define SWZ64(o) ((o) ^ (((o) >> 3) & 0x30))

// ---------------- prep kernels ----------------
__global__ void prep_weights(const float* __restrict__ W0, const float* __restrict__ W1,
                             const float* __restrict__ W2, const float* __restrict__ W3,
                             const float* __restrict__ W4, const float* __restrict__ W5,
                             __nv_bfloat16* __restrict__ WH, __nv_bfloat16* __restrict__ WL)
{
    int idx = blockIdx.x * blockDim.x + threadIdx.x;
    if (idx >= 6 * WT_SZ) return;
    const int layer = idx / WT_SZ;
    const int rem = idx - layer * WT_SZ;
    const int n = rem >> 8, k = rem & 255;
    const int Ks[6] = {64, 64, 256, 256, 256, 256};
    const int Ns[6] = {256, 256, 256, 256, 128, 272};
    const float* Ws[6] = {W0, W1, W2, W3, W4, W5};
    float v = 0.f;
    if (n < Ns[layer] && k < Ks[layer]) v = Ws[layer][(size_t)k * Ns[layer] + n];
    __nv_bfloat16 h = __float2bfloat16(v);
    WH[idx] = h;
    WL[idx] = __float2bfloat16(v - __bfloat162float(h));
}

__global__ void prep_sact(const float* __restrict__ s,
                          __nv_bfloat16* __restrict__ H, __nv_bfloat16* __restrict__ L)
{
    int idx = blockIdx.x * blockDim.x + threadIdx.x;
    if (idx >= T_LEN * 64) return;
    float v = s[idx];
    __nv_bfloat16 h = __float2bfloat16(v);
    H[idx] = h;
    L[idx] = __float2bfloat16(v - __bfloat162float(h));
}

// ---------------- fully fused MLP kernel ----------------
// One CTA = 64 rows, whole network. blockIdx.y: 0 = policy (-> log_pis),
// 1 = obs (-> log_softmax/entropy/tr0). Hidden states live in SMEM only.
// SMEM map (byte offsets from smb):
//   bufA: 0      (H plane 0..32K: 8 slabs x 4KB; L plane 32K..64K)
//   bufB: 65536  (same layout)
//   Wst:  131072 (3 stages x 16KB; H at +0, L at +8192)
#define OFS_A  0
#define OFS_AL 32768
#define OFS_B  65536
#define OFS_BL 98304
#define OFS_W  131072
#define FUSED_SMEM (131072 + 3 * 16384 + 1024)

__global__ __launch_bounds__(256, 1) void mlp_fused(
    const __nv_bfloat16* __restrict__ sH, const __nv_bfloat16* __restrict__ sL,
    const __nv_bfloat16* __restrict__ wtH, const __nv_bfloat16* __restrict__ wtL,
    const float* __restrict__ pb1, const float* __restrict__ pb2, const float* __restrict__ pb3,
    const float* __restrict__ ob1, const float* __restrict__ ob2, const float* __restrict__ ob3,
    const float* __restrict__ a_arr, const float* __restrict__ a_ls,
    float* __restrict__ out_pis, float* __restrict__ out_trs,
    float* __restrict__ out_ent, float* __restrict__ tr0)
{
    extern __shared__ uint8_t dsm[];
    const uint32_t raw = s2u(dsm);
    const uint32_t smb = (raw + 1023u) & ~1023u;
    uint8_t* smp = dsm + (smb - raw);

    const int tid = threadIdx.x, lane = tid & 31, wid = tid >> 5;
    const int warpM = (wid & 1) * 32, warpN = (wid >> 1) * 32;
    const int mat = lane >> 3, rin = lane & 7;
    const int aRow = warpM + ((mat & 1) << 3) + rin;
    const int aKb  = (mat >> 1) << 4;
    const int bRow = warpN + ((mat >> 1) << 3) + rin;
    const int bKb  = (mat & 1) << 4;
    const int g = lane >> 2, c = lane & 3;
    const int row0 = blockIdx.x * 64;
    const bool pol = (blockIdx.y == 0);

    const __nv_bfloat16* w1H = wtH + (size_t)(pol ? 0 : 1) * WT_SZ;
    const __nv_bfloat16* w1L = wtL + (size_t)(pol ? 0 : 1) * WT_SZ;
    const __nv_bfloat16* w2H = wtH + (size_t)(pol ? 2 : 3) * WT_SZ;
    const __nv_bfloat16* w2L = wtL + (size_t)(pol ? 2 : 3) * WT_SZ;
    const __nv_bfloat16* w3H = wtH + (size_t)(pol ? 4 : 5) * WT_SZ;
    const __nv_bfloat16* w3L = wtL + (size_t)(pol ? 4 : 5) * WT_SZ;
    const float* b1 = pol ? pb1 : ob1;
    const float* b2 = pol ? pb2 : ob2;
    const float* b3 = pol ? pb3 : ob3;

    // W staging assignment (identical pattern to validated gemm7)
    const int wrow = tid >> 1, wh = tid & 1;
    const uint32_t wsw0 = SWZ64((uint32_t)(wrow * 64 + wh * 32));
    const uint32_t wsw1 = SWZ64((uint32_t)(wrow * 64 + wh * 32 + 16));

    float acc[2][4][4];

    auto run_gemm = [&](uint32_t ofsA, const __nv_bfloat16* WHb, const __nv_bfloat16* WLb,
                        int nh, int kslabs) {
#pragma unroll
        for (int mt = 0; mt < 2; mt++)
#pragma unroll
            for (int nt = 0; nt < 4; nt++)
#pragma unroll
                for (int q = 0; q < 4; q++) acc[mt][nt][q] = 0.f;

        const __nv_bfloat16* pWH = WHb + (size_t)(nh * 128 + wrow) * WT_KPAD + wh * 16;
        const __nv_bfloat16* pWL = WLb + (size_t)(nh * 128 + wrow) * WT_KPAD + wh * 16;

        auto issueW = [&](int s, int st) {
            uint32_t SB = smb + OFS_W + (uint32_t)st * 16384u;
            cpa16(SB + wsw0, pWH + s * 32);
            cpa16(SB + wsw1, pWH + s * 32 + 8);
            cpa16(SB + 8192 + wsw0, pWL + s * 32);
            cpa16(SB + 8192 + wsw1, pWL + s * 32 + 8);
            CP_COMMIT();
        };
        issueW(0, 0);
        if (kslabs > 1) issueW(1, 1);
#pragma unroll 1
        for (int s = 0; s < kslabs; s++) {
            if (s < kslabs - 1) asm volatile("cp.async.wait_group 1;" ::: "memory");
            else                asm volatile("cp.async.wait_group 0;" ::: "memory");
            __syncthreads();
            const uint32_t WH_ = smb + OFS_W + (uint32_t)(s % 3) * 16384u;
            const uint32_t WL_ = WH_ + 8192;
            const uint32_t AHs = smb + ofsA + (uint32_t)s * 4096u;
            const uint32_t ALs = AHs + 32768u;
#pragma unroll
            for (int ks = 0; ks < 2; ks++) {
                uint32_t bh[2][4], bl[2][4];
#pragma unroll
                for (int p = 0; p < 2; p++) {
                    uint32_t sw = SWZ64((uint32_t)((bRow + p * 16) * 64 + ks * 32 + bKb));
                    LDM4(bh[p], WH_ + sw);
                    LDM4(bl[p], WL_ + sw);
                }
#pragma unroll
                for (int mt = 0; mt < 2; mt++) {
                    uint32_t sw = SWZ64((uint32_t)((aRow + mt * 16) * 64 + ks * 32 + aKb));
                    uint32_t ah[4], al[4];
                    LDM4(ah, AHs + sw);
                    LDM4(al, ALs + sw);
#pragma unroll
                    for (int nt = 0; nt < 4; nt++) {
                        const int p = nt >> 1, ix = (nt & 1) * 2;
                        uint32_t bbh[2] = {bh[p][ix], bh[p][ix + 1]};
                        uint32_t bbl[2] = {bl[p][ix], bl[p][ix + 1]};
                        mma16816(acc[mt][nt], ah, bbh);
                        mma16816(acc[mt][nt], ah, bbl);
                        mma16816(acc[mt][nt], al, bbh);
                    }
                }
            }
            if (s + 2 < kslabs) issueW(s + 2, (s + 2) % 3);
        }
        __syncthreads();   // W buffers free for next call
    };

    // Epilogue: relu(acc + bias), split to bf16 hi/lo, store into slab layout.
    auto store_h = [&](const float* bias, int nh, uint32_t dofsH) {
#pragma unroll
        for (int mt = 0; mt < 2; mt++) {
#pragma unroll
            for (int nt = 0; nt < 4; nt++) {
                const int abscol = nh * 128 + warpN + nt * 8 + c * 2;
                const float bx = bias[abscol], by = bias[abscol + 1];
                float v0 = fmaxf(acc[mt][nt][0] + bx, 0.f);
                float v1 = fmaxf(acc[mt][nt][1] + by, 0.f);
                float v2 = fmaxf(acc[mt][nt][2] + bx, 0.f);
                float v3 = fmaxf(acc[mt][nt][3] + by, 0.f);
                const int r0 = warpM + mt * 16 + g;
                const uint32_t slab = (uint32_t)(abscol >> 5) * 4096u;
                const uint32_t off  = (uint32_t)((abscol & 31) * 2);
                __nv_bfloat16 h0 = __float2bfloat16(v0), h1 = __float2bfloat16(v1);
                __nv_bfloat16 h2 = __float2bfloat16(v2), h3 = __float2bfloat16(v3);
                *(uint32_t*)(smp + dofsH + slab + SWZ64((uint32_t)(r0 * 64) + off)) = pack2(h0, h1);
                *(uint32_t*)(smp + dofsH + 32768 + slab + SWZ64((uint32_t)(r0 * 64) + off)) =
                    pack2(__float2bfloat16(v0 - __bfloat162float(h0)),
                          __float2bfloat16(v1 - __bfloat162float(h1)));
                *(uint32_t*)(smp + dofsH + slab + SWZ64((uint32_t)((r0 + 8) * 64) + off)) = pack2(h2, h3);
                *(uint32_t*)(smp + dofsH + 32768 + slab + SWZ64((uint32_t)((r0 + 8) * 64) + off)) =
                    pack2(__float2bfloat16(v2 - __bfloat162float(h2)),
                          __float2bfloat16(v3 - __bfloat162float(h3)));
            }
        }
    };

    // ---- stage s input into bufA (joins the first cp.async group) ----
    {
        const int m = tid >> 2, c4 = tid & 3;
        const int kb0 = c4 * 32, kb1 = c4 * 32 + 16;
        const __nv_bfloat16* srcH = sH + (size_t)(row0 + m) * 64;
        const __nv_bfloat16* srcL = sL + (size_t)(row0 + m) * 64;
        cpa16(smb + OFS_A + (uint32_t)(kb0 >> 6) * 4096u + SWZ64((uint32_t)(m * 64 + (kb0 & 63))),
              srcH + kb0 / 2);
        cpa16(smb + OFS_A + (uint32_t)(kb1 >> 6) * 4096u + SWZ64((uint32_t)(m * 64 + (kb1 & 63))),
              srcH + kb1 / 2);
        cpa16(smb + OFS_AL + (uint32_t)(kb0 >> 6) * 4096u + SWZ64((uint32_t)(m * 64 + (kb0 & 63))),
              srcL + kb0 / 2);
        cpa16(smb + OFS_AL + (uint32_t)(kb1 >> 6) * 4096u + SWZ64((uint32_t)(m * 64 + (kb1 & 63))),
              srcL + kb1 / 2);
    }

    // ---- Layer 1: s(bufA) -> h1(bufB), K=64 (2 slabs), N=256 ----
    run_gemm(OFS_A, w1H, w1L, 0, 2);  store_h(b1, 0, OFS_B);
    run_gemm(OFS_A, w1H, w1L, 1, 2);  store_h(b1, 1, OFS_B);
    __syncthreads();
    // ---- Layer 2: h1(bufB) -> h2(bufA), K=256 (8 slabs), N=256 ----
    run_gemm(OFS_B, w2H, w2L, 0, 8);  store_h(b2, 0, OFS_A);
    run_gemm(OFS_B, w2H, w2L, 1, 8);  store_h(b2, 1, OFS_A);
    __syncthreads();

    if (pol) {
        // ---- Layer 3 policy: h2 -> mean (N=128) + fused log_pis ----
        run_gemm(OFS_A, w3H, w3L, 0, 8);
        float lsv[8]; float lsum = 0.f;
#pragma unroll
        for (int a = 0; a < 8; a++) {
            float l = tanhf(a_ls[a]);
            l = -5.0f + 3.5f * (l + 1.0f);
            lsv[a] = l; lsum += l;
        }
        const float cst = -lsum - 4.0f * 1.8378770664093453f;
        const float is0 = expf(-lsv[c * 2]), is1 = expf(-lsv[c * 2 + 1]);
#pragma unroll
        for (int mt = 0; mt < 2; mt++) {
            const int rw = row0 + warpM + mt * 16 + g;
            const float a00 = a_arr[(size_t)rw * 8 + c * 2];
            const float a01 = a_arr[(size_t)rw * 8 + c * 2 + 1];
            const float a10 = a_arr[(size_t)(rw + 8) * 8 + c * 2];
            const float a11 = a_arr[(size_t)(rw + 8) * 8 + c * 2 + 1];
#pragma unroll
            for (int nt = 0; nt < 4; nt++) {
                const int col = warpN + nt * 8 + c * 2;
                const float bx = b3[col], by = b3[col + 1];
                const int cc = (warpN >> 3) + nt;
                float m00 = fminf(fmaxf(acc[mt][nt][0] + bx, -10.f), 10.f);
                float m01 = fminf(fmaxf(acc[mt][nt][1] + by, -10.f), 10.f);
                float m10 = fminf(fmaxf(acc[mt][nt][2] + bx, -10.f), 10.f);
                float m11 = fminf(fmaxf(acc[mt][nt][3] + by, -10.f), 10.f);
                float z, s0, s1;
                z = (a00 - m00) * is0; s0 = z * z;
                z = (a01 - m01) * is1; s0 = fmaf(z, z, s0);
                z = (a10 - m10) * is0; s1 = z * z;
                z = (a11 - m11) * is1; s1 = fmaf(z, z, s1);
                s0 += __shfl_xor_sync(0xffffffffu, s0, 1);
                s0 += __shfl_xor_sync(0xffffffffu, s0, 2);
                s1 += __shfl_xor_sync(0xffffffffu, s1, 1);
                s1 += __shfl_xor_sync(0xffffffffu, s1, 2);
                if (c == 0) {
                    out_pis[(size_t)rw * 16 + cc]       = -0.5f * s0 + cst;
                    out_pis[(size_t)(rw + 8) * 16 + cc] = -0.5f * s1 + cst;
                }
            }
        }
    } else {
        // ---- Layer 3 obs: h2 -> logits (N=272, 3 halves) + fused log_softmax ----
#pragma unroll 1
        for (int nh = 0; nh < 3; nh++) {
            run_gemm(OFS_A, w3H, w3L, nh, 8);
#pragma unroll
            for (int mt = 0; mt < 2; mt++) {
                const int rw = row0 + warpM + mt * 16 + g;
#pragma unroll
                for (int ntp = 0; ntp < 2; ntp++) {
                    const int base = nh * 128 + warpN + ntp * 16;
                    if (base >= 272) continue;
                    const int n0 = ntp * 2, n1 = ntp * 2 + 1;
                    const int cA = base + c * 2, cB = base + 8 + c * 2;
                    const float bv0 = b3[cA], bv1 = b3[cA + 1];
                    const float bv2 = b3[cB], bv3 = b3[cB + 1];
                    float v[2][4];
                    v[0][0] = acc[mt][n0][0] + bv0; v[0][1] = acc[mt][n0][1] + bv1;
                    v[0][2] = acc[mt][n1][0] + bv2; v[0][3] = acc[mt][n1][1] + bv3;
                    v[1][0] = acc[mt][n0][2] + bv0; v[1][1] = acc[mt][n0][3] + bv1;
                    v[1][2] = acc[mt][n1][2] + bv2; v[1][3] = acc[mt][n1][3] + bv3;
                    const int gi = base >> 4;
#pragma unroll
                    for (int r = 0; r < 2; r++) {
                        const int row = rw + r * 8;
                        float mx = fmaxf(fmaxf(v[r][0], v[r][1]), fmaxf(v[r][2], v[r][3]));
                        mx = fmaxf(mx, __shfl_xor_sync(0xffffffffu, mx, 1));
                        mx = fmaxf(mx, __shfl_xor_sync(0xffffffffu, mx, 2));
                        float s = 0.f, ws = 0.f;
#pragma unroll
                        for (int q = 0; q < 4; q++) {
                            float d = v[r][q] - mx;
                            float e = __expf(d);
                            s += e; ws = fmaf(d, e, ws);
                        }
                        s  += __shfl_xor_sync(0xffffffffu, s, 1);
                        s  += __shfl_xor_sync(0xffffffffu, s, 2);
                        ws += __shfl_xor_sync(0xffffffffu, ws, 1);
                        ws += __shfl_xor_sync(0xffffffffu, ws, 2);
                        const float ls = __logf(s), lse = mx + ls;
                        if (gi < 16) {
                            if (row >= 1) {
                                float* o = out_trs + (size_t)(row - 1) * 256 + gi * 16;
                                *(float2*)&o[c * 2]     = make_float2(v[r][0] - lse, v[r][1] - lse);
                                *(float2*)&o[8 + c * 2] = make_float2(v[r][2] - lse, v[r][3] - lse);
                                if (c == 0) out_ent[(size_t)(row - 1) * 16 + gi] = ls - ws / s;
                            }
                        } else if (row == 0) {
                            tr0[c * 2]     = v[r][0] - lse;
                            tr0[c * 2 + 1] = v[r][1] - lse;
                            tr0[8 + c * 2]     = v[r][2] - lse;
                            tr0[8 + c * 2 + 1] = v[r][3] - lse;
                        }
                    }
                }
            }
        }
    }
}

// ---------------- scan pass 1: factorized log-semiring matmul ----------------
__global__ __launch_bounds__(256) void pass1_kernel(
    const float* __restrict__ trs, const float* __restrict__ pis, float* __restrict__ Cmat)
{
    const int g = blockIdx.x, tid = threadIdx.x;
    const int i = tid >> 4, j = tid & 15;
    const int t0 = g * CHUNK, t1 = min(t0 + CHUNK, NTRANS);
    const unsigned fm = 0xffffffffu;

    __shared__ float Ps[256];
    __shared__ float QT[16 * 17];
    __shared__ float CMX[16];

    float C = trs[(size_t)t0 * 256 + tid] + pis[(size_t)(t0 + 1) * 16 + j];

    for (int t = t0 + 1; t < t1; t++) {
        float mv = trs[(size_t)t * 256 + j * 16 + i] + pis[(size_t)(t + 1) * 16 + i];
        float rmx = C;
        rmx = fmaxf(rmx, __shfl_xor_sync(fm, rmx, 1));
        rmx = fmaxf(rmx, __shfl_xor_sync(fm, rmx, 2));
        rmx = fmaxf(rmx, __shfl_xor_sync(fm, rmx, 4));
        rmx = fmaxf(rmx, __shfl_xor_sync(fm, rmx, 8));
        float cmx = mv;
        cmx = fmaxf(cmx, __shfl_xor_sync(fm, cmx, 1));
        cmx = fmaxf(cmx, __shfl_xor_sync(fm, cmx, 2));
        cmx = fmaxf(cmx, __shfl_xor_sync(fm, cmx, 4));
        cmx = fmaxf(cmx, __shfl_xor_sync(fm, cmx, 8));

        __syncthreads();
        Ps[tid] = __expf(C - rmx);
        QT[i * 17 + j] = __expf(mv - cmx);
        if (j == 0) CMX[i] = cmx;
        __syncthreads();

        float dot = 0.f;
#pragma unroll
        for (int k = 0; k < 16; k++)
            dot = fmaf(Ps[i * 16 + k], QT[j * 17 + k], dot);
        C = rmx + CMX[j] + __logf(dot);
    }
    Cmat[g * 256 + tid] = C;
}

// ---------------- group prefix/suffix products ----------------
__global__ __launch_bounds__(256) void superprod_kernel(
    const float* __restrict__ Cmat, float* __restrict__ P, float* __restrict__ Suf)
{
    const int s = blockIdx.x & 15, dir = blockIdx.x >> 4, tid = threadIdx.x;
    const int i = tid >> 4, j = tid & 15;
    __shared__ float Cs[2][256], Ms[256];
    int cb = 0;
    if (dir == 0) {
        Cs[0][tid] = Cmat[(s*16) * 256 + tid];
        P[(s*16) * 256 + tid] = Cs[0][tid];
        for (int r = 1; r < 16; r++) {
            float mv = Cmat[(s*16+r) * 256 + tid];
            __syncthreads(); Ms[tid] = mv; __syncthreads();
            float tmp[16], mx = -FLT_MAX;
#pragma unroll
            for (int k = 0; k < 16; k++) { tmp[k] = Cs[cb][i*16+k] + Ms[k*16+j]; mx = fmaxf(mx, tmp[k]); }
            float ss = 0.f;
#pragma unroll
            for (int k = 0; k < 16; k++) ss += __expf(tmp[k] - mx);
            float res = mx + __logf(ss);
            Cs[cb^1][tid] = res;
            P[(s*16+r) * 256 + tid] = res;
            cb ^= 1;
        }
    } else {
        Cs[0][tid] = Cmat[(s*16+15) * 256 + tid];
        Suf[(s*16+15) * 256 + tid] = Cs[0][tid];
        for (int r = 14; r >= 0; r--) {
            float mv = Cmat[(s*16+r) * 256 + tid];
            __syncthreads(); Ms[tid] = mv; __syncthreads();
            float tmp[16], mx = -FLT_MAX;
#pragma unroll
            for (int k = 0; k < 16; k++) { tmp[k] = Ms[i*16+k] + Cs[cb][k*16+j]; mx = fmaxf(mx, tmp[k]); }
            float ss = 0.f;
#pragma unroll
            for (int k = 0; k < 16; k++) ss += __expf(tmp[k] - mx);
            float res = mx + __logf(ss);
            Cs[cb^1][tid] = res;
            Suf[(s*16+r) * 256 + tid] = res;
            cb ^= 1;
        }
    }
}

// ---------------- serial combine ----------------
__global__ void combine2_kernel(const float* __restrict__ P, const float* __restrict__ tr0,
                                const float* __restrict__ pis, float* __restrict__ Vs,
                                float* __restrict__ Wsv, float* __restrict__ out_beta)
{
    const int lane = threadIdx.x;
    if (lane >= 16) return;
    const unsigned mask = 0xFFFFu;
    if (blockIdx.x == 0) {
        float v = tr0[lane] + pis[lane];
        Vs[lane] = v;
        for (int s = 0; s < NSUPER; s++) {
            const float* S = P + (s*16+15) * 256;
            float tmp[16];
#pragma unroll
            for (int i = 0; i < 16; i++) tmp[i] = __shfl_sync(mask, v, i) + S[i*16+lane];
            float mx = tmp[0];
#pragma unroll
            for (int i = 1; i < 16; i++) mx = fmaxf(mx, tmp[i]);
            float ss = 0.f;
#pragma unroll
            for (int i = 0; i < 16; i++) ss += __expf(tmp[i] - mx);
            v = mx + __logf(ss);
            Vs[(s+1)*16 + lane] = v;
        }
    } else {
        float w = 0.f;
        Wsv[NSUPER*16 + lane] = 0.f;
        out_beta[(size_t)(T_LEN-1) * 16 + lane] = 0.f;
        for (int s = NSUPER - 1; s >= 0; s--) {
            const float* S = P + (s*16+15) * 256 + lane * 16;
            float tmp[16];
#pragma unroll
            for (int j = 0; j < 16; j++) tmp[j] = __shfl_sync(mask, w, j) + S[j];
            float mx = tmp[0];
#pragma unroll
            for (int j = 1; j < 16; j++) mx = fmaxf(mx, tmp[j]);
            float ss = 0.f;
#pragma unroll
            for (int j = 0; j < 16; j++) ss += __expf(tmp[j] - mx);
            w = mx + __logf(ss);
            Wsv[s*16 + lane] = w;
        }
    }
}

// ---------------- scan pass 2 ----------------
__global__ void pass2_kernel(const float* __restrict__ trs, const float* __restrict__ pis,
                             const float* __restrict__ P, const float* __restrict__ Suf,
                             const float* __restrict__ Vs, const float* __restrict__ Wsv,
                             float* __restrict__ out_alpha, float* __restrict__ out_beta)
{
    const int lane = threadIdx.x;
    if (lane >= 16) return;
    const unsigned mask = 0xFFFFu;
    const int b = blockIdx.x;
    if (b < G_CHUNKS) {
        const int g = b, s = g >> 4, r = g & 15;
        const int t0 = g * CHUNK, t1 = min(t0 + CHUNK, NTRANS);
        float v;
        {
            float vs = Vs[s*16 + lane];
            if (r == 0) v = vs;
            else {
                const float* Pm = P + (s*16 + r - 1) * 256;
                float tmp[16];
#pragma unroll
                for (int i = 0; i < 16; i++) tmp[i] = __shfl_sync(mask, vs, i) + Pm[i*16+lane];
                float mx = tmp[0];
#pragma unroll
                for (int i = 1; i < 16; i++) mx = fmaxf(mx, tmp[i]);
                float ss = 0.f;
#pragma unroll
                for (int i = 0; i < 16; i++) ss += __expf(tmp[i] - mx);
                v = mx + __logf(ss);
            }
        }
        if (g == 0) out_alpha[lane] = v;
        for (int t = t0; t < t1; t++) {
            const float* M = trs + (size_t)t * 256;
            float tmp[16];
#pragma unroll
            for (int i = 0; i < 16; i++) tmp[i] = __shfl_sync(mask, v, i) + M[i*16+lane];
            float mx = tmp[0];
#pragma unroll
            for (int i = 1; i < 16; i++) mx = fmaxf(mx, tmp[i]);
            float ss = 0.f;
#pragma unroll
            for (int i = 0; i < 16; i++) ss += __expf(tmp[i] - mx);
            v = mx + __logf(ss) + pis[(size_t)(t+1) * 16 + lane];
            out_alpha[(size_t)(t+1) * 16 + lane] = v;
        }
    } else {
        const int g = b - G_CHUNKS, s = g >> 4, r = g & 15;
        const int t0 = g * CHUNK, t1 = min(t0 + CHUNK, NTRANS);
        float w;
        {
            float wsv = Wsv[(s+1)*16 + lane];
            if (r == 15) w = wsv;
            else {
                const float* Sf = Suf + (s*16 + r + 1) * 256 + lane * 16;
                float tmp[16];
#pragma unroll
                for (int j = 0; j < 16; j++) tmp[j] = Sf[j] + __shfl_sync(mask, wsv, j);
                float mx = tmp[0];
#pragma unroll
                for (int j = 1; j < 16; j++) mx = fmaxf(mx, tmp[j]);
                float ss = 0.f;
#pragma unroll
                for (int j = 0; j < 16; j++) ss += __expf(tmp[j] - mx);
                w = mx + __logf(ss);
            }
        }
        for (int t = t1 - 1; t >= t0; t--) {
            const float* M = trs + (size_t)t * 256 + lane * 16;
            float u = w + pis[(size_t)(t+1) * 16 + lane];
            float tmp[16];
#pragma unroll
            for (int j = 0; j < 16; j++) tmp[j] = __shfl_sync(mask, u, j) + M[j];
            float mx = tmp[0];
#pragma unroll
            for (int j = 1; j < 16; j++) mx = fmaxf(mx, tmp[j]);
            float ss = 0.f;
#pragma unroll
            for (int j = 0; j < 16; j++) ss += __expf(tmp[j] - mx);
            w = mx + __logf(ss);
            out_beta[(size_t)t * 16 + lane] = w;
        }
    }
}

// ---------------- host launcher ----------------
extern "C" void kernel_launch(void* const* d_in, const int* in_sizes, int n_in,
                              void* d_out, int out_size)
{
    const float* s_arr = (const float*)d_in[0];
    const float* a_arr = (const float*)d_in[1];
    const float* pW1 = (const float*)d_in[2];  const float* pb1 = (const float*)d_in[3];
    const float* pW2 = (const float*)d_in[4];  const float* pb2 = (const float*)d_in[5];
    const float* pW3 = (const float*)d_in[6];  const float* pb3 = (const float*)d_in[7];
    const float* oW1 = (const float*)d_in[8];  const float* ob1 = (const float*)d_in[9];
    const float* oW2 = (const float*)d_in[10]; const float* ob2 = (const float*)d_in[11];
    const float* oW3 = (const float*)d_in[12]; const float* ob3 = (const float*)d_in[13];
    const float* als = (const float*)d_in[14];

    float* out = (float*)d_out;
    float* out_alpha = out + OFF_ALPHA;
    float* out_beta  = out + OFF_BETA;
    float* out_trs   = out + OFF_TRS;
    float* out_pis   = out + OFF_PIS;
    float* out_ent   = out + OFF_ENT;

    __nv_bfloat16 *sH, *sL, *wtH, *wtL;
    float *Cmat, *Pm, *Sf, *Vs, *Wsv, *tr0;
    cudaGetSymbolAddress((void**)&sH, g_sH);   cudaGetSymbolAddress((void**)&sL, g_sL);
    cudaGetSymbolAddress((void**)&wtH, g_wtH); cudaGetSymbolAddress((void**)&wtL, g_wtL);
    cudaGetSymbolAddress((void**)&Cmat, g_Cmat);
    cudaGetSymbolAddress((void**)&Pm, g_P);
    cudaGetSymbolAddress((void**)&Sf, g_Suf);
    cudaGetSymbolAddress((void**)&Vs, g_Vs);
    cudaGetSymbolAddress((void**)&Wsv, g_Wsv);
    cudaGetSymbolAddress((void**)&tr0, g_tr0);

    cudaFuncSetAttribute(mlp_fused, cudaFuncAttributeMaxDynamicSharedMemorySize, FUSED_SMEM);

    prep_weights<<<(6 * WT_SZ + 255) / 256, 256>>>(pW1, oW1, pW2, oW2, pW3, oW3, wtH, wtL);
    prep_sact<<<(T_LEN * 64 + 255) / 256, 256>>>(s_arr, sH, sL);

    mlp_fused<<<dim3(T_LEN / 64, 2), 256, FUSED_SMEM>>>(
        sH, sL, wtH, wtL, pb1, pb2, pb3, ob1, ob2, ob3,
        a_arr, als, out_pis, out_trs, out_ent, tr0);

    pass1_kernel<<<G_CHUNKS, 256>>>(out_trs, out_pis, Cmat);
    superprod_kernel<<<2 * NSUPER, 256>>>(Cmat, Pm, Sf);
    combine2_kernel<<<2, 32>>>(Pm, tr0, out_pis, Vs, Wsv, out_beta);
    pass2_kernel<<<2 * G_CHUNKS, 32>>>(out_trs, out_pis, Pm, Sf, Vs, Wsv,
                                       out_alpha, out_beta);
}